// round 5
// baseline (speedup 1.0000x reference)
#include <cuda_runtime.h>
#include <cuda_bf16.h>
#include <stdint.h>

// ======================= fragment-packed weight image =======================
#define OFF_B1    0
#define OFF_B0    28672
#define OFF_B1B   36864
#define OFF_BIAS1 40960
#define OFF_B0F   43008
#define OFF_B1F   44032
#define OFF_W2F   45056
#define OFF_B2    47104
#define PACK_BYTES 47120

__device__ __align__(16) unsigned char g_pack[PACK_BYTES];

// ======================= helpers =======================
__device__ __forceinline__ uint32_t pack_bf16x2(float a, float b) {
    __nv_bfloat16 ha = __float2bfloat16(a), hb = __float2bfloat16(b);
    return (uint32_t)__bfloat16_as_ushort(ha) | ((uint32_t)__bfloat16_as_ushort(hb) << 16);
}
__device__ __forceinline__ void bsplit(float f, float& h, float& l) {
    __nv_bfloat16 hb = __float2bfloat16(f);
    h = __bfloat162float(hb);
    l = f - h;
}
__device__ __forceinline__ void split_pack2(float f0, float f1, uint32_t& hr, uint32_t& lr) {
    float h0, l0, h1, l1;
    bsplit(f0, h0, l0);
    bsplit(f1, h1, l1);
    hr = pack_bf16x2(h0, h1);
    lr = pack_bf16x2(l0, l1);
}
__device__ __forceinline__ void mma16816(float* c, const uint32_t* a, uint32_t b0, uint32_t b1) {
    asm volatile(
        "mma.sync.aligned.m16n8k16.row.col.f32.bf16.bf16.f32 "
        "{%0,%1,%2,%3}, {%4,%5,%6,%7}, {%8,%9}, {%0,%1,%2,%3};"
        : "+f"(c[0]), "+f"(c[1]), "+f"(c[2]), "+f"(c[3])
        : "r"(a[0]), "r"(a[1]), "r"(a[2]), "r"(a[3]), "r"(b0), "r"(b1));
}

// ======================= prep kernel =======================
__device__ __forceinline__ float getW1c(const float* Ww, const float* Wb, int n, int k) {
    if (k >= 98) return 0.f;
    if (n < 32) return Ww[n * 98 + k];
    int kk = k + 49; if (kk >= 98) kk -= 98;
    return Wb[(n - 32) * 98 + kk];
}

__global__ void prep_kernel(const float* __restrict__ Ww, const float* __restrict__ Wb,
                            const float* __restrict__ W0, const float* __restrict__ W1,
                            const float* __restrict__ bw, const float* __restrict__ bb,
                            const float* __restrict__ b0, const float* __restrict__ b1,
                            const float* __restrict__ W2, const float* __restrict__ b2)
{
    const int tid = threadIdx.x;  // 256 threads
    char* gp = (char*)g_pack;

    for (int idx = tid; idx < 8 * 7 * 32; idx += 256) {
        int lane = idx & 31, t = idx >> 5;
        int kt = t % 7, nt = t / 7;
        int n = nt * 8 + (lane >> 2);
        int k0 = kt * 16 + (lane & 3) * 2;
        float w[4] = { getW1c(Ww, Wb, n, k0),     getW1c(Ww, Wb, n, k0 + 1),
                       getW1c(Ww, Wb, n, k0 + 8), getW1c(Ww, Wb, n, k0 + 9) };
        float h[4], l[4];
        for (int i = 0; i < 4; i++) bsplit(w[i], h[i], l[i]);
        uint4 v;
        v.x = pack_bf16x2(h[0], h[1]); v.y = pack_bf16x2(h[2], h[3]);
        v.z = pack_bf16x2(l[0], l[1]); v.w = pack_bf16x2(l[2], l[3]);
        ((uint4*)(gp + OFF_B1))[idx] = v;
    }
    for (int idx = tid; idx < 4 * 4 * 32; idx += 256) {
        int lane = idx & 31, t = idx >> 5;
        int kt = t & 3, nt = t >> 2;
        int n = nt * 8 + (lane >> 2);
        int k0 = kt * 16 + (lane & 3) * 2;
        float w[4] = { W0[n * 64 + k0],     W0[n * 64 + k0 + 1],
                       W0[n * 64 + k0 + 8], W0[n * 64 + k0 + 9] };
        float h[4], l[4];
        for (int i = 0; i < 4; i++) bsplit(w[i], h[i], l[i]);
        uint4 v;
        v.x = pack_bf16x2(h[0], h[1]); v.y = pack_bf16x2(h[2], h[3]);
        v.z = pack_bf16x2(l[0], l[1]); v.w = pack_bf16x2(l[2], l[3]);
        ((uint4*)(gp + OFF_B0))[idx] = v;
    }
    for (int idx = tid; idx < 4 * 2 * 32; idx += 256) {
        int lane = idx & 31, t = idx >> 5;
        int kt = t & 1, nt = t >> 1;
        int n = nt * 8 + (lane >> 2);
        int k0 = kt * 16 + (lane & 3) * 2;
        float w[4] = { W1[n * 32 + k0],     W1[n * 32 + k0 + 1],
                       W1[n * 32 + k0 + 8], W1[n * 32 + k0 + 9] };
        float h[4], l[4];
        for (int i = 0; i < 4; i++) bsplit(w[i], h[i], l[i]);
        uint4 v;
        v.x = pack_bf16x2(h[0], h[1]); v.y = pack_bf16x2(h[2], h[3]);
        v.z = pack_bf16x2(l[0], l[1]); v.w = pack_bf16x2(l[2], l[3]);
        ((uint4*)(gp + OFF_B1B))[idx] = v;
    }
    for (int idx = tid; idx < 4 * 32; idx += 256) {
        int lane = idx & 31, j = idx >> 5;
        int c = j * 8 + (lane & 3) * 2;
        float4 bf; bf.x = bw[c]; bf.y = bw[c + 1]; bf.z = bb[c]; bf.w = bb[c + 1];
        ((float4*)(gp + OFF_BIAS1))[idx] = bf;
        float2 f0; f0.x = b0[c]; f0.y = b0[c + 1];
        ((float2*)(gp + OFF_B0F))[idx] = f0;
        float2 f1; f1.x = b1[c]; f1.y = b1[c + 1];
        ((float2*)(gp + OFF_B1F))[idx] = f1;
        float4 w2; w2.x = W2[c]; w2.y = W2[c + 1]; w2.z = W2[32 + c]; w2.w = W2[32 + c + 1];
        ((float4*)(gp + OFF_W2F))[idx] = w2;
    }
    if (tid == 0) *((float*)(gp + OFF_B2)) = b2[0];
}

// ======================= main fused kernel =======================
// smem: stH[128][56] + stL[128][56] pre-split bf16x2 pair words (skewed), spov[128]
#define PAIR_STRIDE 56
#define SMEM_WORDS (128 * PAIR_STRIDE * 2 + 128)   // 14464 words = 57856 B

__global__ void __launch_bounds__(128, 3)
nnue_main(const float* __restrict__ pov, const float* __restrict__ white,
          const float* __restrict__ black, float* __restrict__ out, int Btot)
{
    extern __shared__ uint32_t sh[];
    uint32_t* stH  = sh;
    uint32_t* stL  = sh + 128 * PAIR_STRIDE;
    float*    spov = (float*)(sh + 2 * 128 * PAIR_STRIDE);

    const int tid  = threadIdx.x;
    const int warp = tid >> 5;
    const int lane = tid & 31;
    const int q    = lane >> 2;
    const int qp   = lane & 3;
    const long long cbase = (long long)blockIdx.x * 128;

    // ---- zero pad pairs 49..55 of every row (B1 weights there are 0, but avoid NaN garbage) ----
    for (int i = tid; i < 128 * 7; i += 128) {
        int s = i / 7, pp = 49 + (i - s * 7);
        int off = pp + 4 * (s & 7); if (off >= PAIR_STRIDE) off -= PAIR_STRIDE;
        stH[s * PAIR_STRIDE + off] = 0u;
        stL[s * PAIR_STRIDE + off] = 0u;
    }

    // ---- stage inputs, pre-split into hi/lo bf16x2 pair words ----
    if (cbase + 128 <= (long long)Btot) {
        const float* wb = white + cbase * 49;
        const float* bb = black + cbase * 49;
        #pragma unroll 1
        for (int it = 0; it < 49; it++) {
            int g = it * 128 + tid;          // pair index 0..6271
            int s = g / 49, p = g - s * 49;  // row, pair-in-row
            int c0 = 2 * p, c1 = c0 + 1;
            float f0 = (c0 < 49) ? __ldcs(wb + s * 49 + c0) : __ldcs(bb + s * 49 + c0 - 49);
            float f1 = (c1 < 49) ? __ldcs(wb + s * 49 + c1) : __ldcs(bb + s * 49 + c1 - 49);
            uint32_t hi, lo;
            split_pack2(f0, f1, hi, lo);
            int off = p + 4 * (s & 7); if (off >= PAIR_STRIDE) off -= PAIR_STRIDE;
            stH[s * PAIR_STRIDE + off] = hi;
            stL[s * PAIR_STRIDE + off] = lo;
        }
        spov[tid] = __ldcs(pov + cbase + tid);
    } else {
        #pragma unroll 1
        for (int it = 0; it < 49; it++) {
            int g = it * 128 + tid;
            int s = g / 49, p = g - s * 49;
            long long row = cbase + s;
            float f0 = 0.f, f1 = 0.f;
            if (row < (long long)Btot) {
                int c0 = 2 * p, c1 = c0 + 1;
                f0 = (c0 < 49) ? white[row * 49 + c0] : black[row * 49 + c0 - 49];
                f1 = (c1 < 49) ? white[row * 49 + c1] : black[row * 49 + c1 - 49];
            }
            uint32_t hi, lo;
            split_pack2(f0, f1, hi, lo);
            int off = p + 4 * (s & 7); if (off >= PAIR_STRIDE) off -= PAIR_STRIDE;
            stH[s * PAIR_STRIDE + off] = hi;
            stL[s * PAIR_STRIDE + off] = lo;
        }
        spov[tid] = (cbase + tid < (long long)Btot) ? pov[cbase + tid] : 0.f;
    }
    __syncthreads();

    const uint4*  B1u  = (const uint4*)(g_pack + OFF_B1);
    const uint4*  B0u  = (const uint4*)(g_pack + OFF_B0);
    const uint4*  B1bu = (const uint4*)(g_pack + OFF_B1B);
    const float4* bia1 = (const float4*)(g_pack + OFF_BIAS1);
    const float2* b0f  = (const float2*)(g_pack + OFF_B0F);
    const float2* b1f  = (const float2*)(g_pack + OFF_B1F);
    const float4* w2f  = (const float4*)(g_pack + OFF_W2F);

    const int rbase = warp * 32;
    const int u = qp + 4 * q;   // skew offset for this lane's rows (row&7 == q)
    int rb[2][2];
    rb[0][0] = (rbase + q) * PAIR_STRIDE;
    rb[0][1] = (rbase + q + 8) * PAIR_STRIDE;
    rb[1][0] = (rbase + q + 16) * PAIR_STRIDE;
    rb[1][1] = (rbase + q + 24) * PAIR_STRIDE;

    // ================= layer 1: both m-tiles share every B fragment =================
    float cw[4][2][4], cb[4][2][4];
    #pragma unroll
    for (int j = 0; j < 4; j++)
        #pragma unroll
        for (int mi = 0; mi < 2; mi++)
            #pragma unroll
            for (int i = 0; i < 4; i++) { cw[j][mi][i] = 0.f; cb[j][mi][i] = 0.f; }

    #pragma unroll
    for (int kt = 0; kt < 7; kt++) {
        int o0 = 8 * kt + u;
        int m0 = (o0 >= PAIR_STRIDE) ? o0 - PAIR_STRIDE : o0;
        int o1 = o0 + 4;
        int m1 = (o1 >= PAIR_STRIDE) ? o1 - PAIR_STRIDE : o1;
        uint32_t ah[2][4], al[2][4];
        #pragma unroll
        for (int mi = 0; mi < 2; mi++) {
            ah[mi][0] = stH[rb[mi][0] + m0];
            ah[mi][1] = stH[rb[mi][1] + m0];
            ah[mi][2] = stH[rb[mi][0] + m1];
            ah[mi][3] = stH[rb[mi][1] + m1];
            al[mi][0] = stL[rb[mi][0] + m0];
            al[mi][1] = stL[rb[mi][1] + m0];
            al[mi][2] = stL[rb[mi][0] + m1];
            al[mi][3] = stL[rb[mi][1] + m1];
        }
        #pragma unroll
        for (int j = 0; j < 4; j++) {
            uint4 Bw = __ldg(B1u + (j * 7 + kt) * 32 + lane);
            uint4 Bb = __ldg(B1u + ((j + 4) * 7 + kt) * 32 + lane);
            #pragma unroll
            for (int mi = 0; mi < 2; mi++) {
                mma16816(cw[j][mi], ah[mi], Bw.x, Bw.y);
                mma16816(cw[j][mi], al[mi], Bw.x, Bw.y);
                mma16816(cw[j][mi], ah[mi], Bw.z, Bw.w);
                mma16816(cb[j][mi], ah[mi], Bb.x, Bb.y);
                mma16816(cb[j][mi], al[mi], Bb.x, Bb.y);
                mma16816(cb[j][mi], ah[mi], Bb.z, Bb.w);
            }
        }
    }

    // ================= per-tile tail (sequential: keeps registers low) =================
    const float b2v = *((const float*)(g_pack + OFF_B2));
    #pragma unroll
    for (int mi = 0; mi < 2; mi++) {
        float pv0 = spov[rbase + mi * 16 + q];
        float pv1 = spov[rbase + mi * 16 + q + 8];
        float pm0 = 1.f - pv0, pm1 = 1.f - pv1;

        // ---- epilogue 1: bias + pov mix + relu -> layer-0 A frags ----
        uint32_t a0h[4][4], a0l[4][4];
        #pragma unroll
        for (int j = 0; j < 4; j++) {
            float4 bi = __ldg(bia1 + j * 32 + lane);
            float w0 = cw[j][mi][0] + bi.x, w1 = cw[j][mi][1] + bi.y;
            float w2_ = cw[j][mi][2] + bi.x, w3 = cw[j][mi][3] + bi.y;
            float bb0 = cb[j][mi][0] + bi.z, bb1 = cb[j][mi][1] + bi.w;
            float bb2 = cb[j][mi][2] + bi.z, bb3 = cb[j][mi][3] + bi.w;
            float vA0 = fmaxf(fmaf(pv0, w0, pm0 * bb0), 0.f);
            float vA1 = fmaxf(fmaf(pv0, w1, pm0 * bb1), 0.f);
            float vA2 = fmaxf(fmaf(pv1, w2_, pm1 * bb2), 0.f);
            float vA3 = fmaxf(fmaf(pv1, w3, pm1 * bb3), 0.f);
            float vB0 = fmaxf(fmaf(pv0, bb0, pm0 * w0), 0.f);
            float vB1 = fmaxf(fmaf(pv0, bb1, pm0 * w1), 0.f);
            float vB2 = fmaxf(fmaf(pv1, bb2, pm1 * w2_), 0.f);
            float vB3 = fmaxf(fmaf(pv1, bb3, pm1 * w3), 0.f);
            int ktw = j >> 1;
            int pos = (j & 1) ? 2 : 0;
            split_pack2(vA0, vA1, a0h[ktw][pos],     a0l[ktw][pos]);
            split_pack2(vA2, vA3, a0h[ktw][pos + 1], a0l[ktw][pos + 1]);
            split_pack2(vB0, vB1, a0h[ktw + 2][pos],     a0l[ktw + 2][pos]);
            split_pack2(vB2, vB3, a0h[ktw + 2][pos + 1], a0l[ktw + 2][pos + 1]);
        }

        // ---- layer 0 ----
        float xv[4][4];
        uint32_t a1h[2][4], a1l[2][4];
        #pragma unroll
        for (int n = 0; n < 4; n++) {
            float c0[4] = {0.f, 0.f, 0.f, 0.f};
            #pragma unroll
            for (int kt = 0; kt < 4; kt++) {
                uint4 Bq = __ldg(B0u + (n * 4 + kt) * 32 + lane);
                mma16816(c0, a0h[kt], Bq.x, Bq.y);
                mma16816(c0, a0l[kt], Bq.x, Bq.y);
                mma16816(c0, a0h[kt], Bq.z, Bq.w);
            }
            float2 bz = __ldg(b0f + n * 32 + lane);
            float x0 = fmaxf(c0[0] + bz.x, 0.f);
            float x1 = fmaxf(c0[1] + bz.y, 0.f);
            float x2 = fmaxf(c0[2] + bz.x, 0.f);
            float x3 = fmaxf(c0[3] + bz.y, 0.f);
            xv[n][0] = x0; xv[n][1] = x1; xv[n][2] = x2; xv[n][3] = x3;
            int ktw = n >> 1;
            int pos = (n & 1) ? 2 : 0;
            split_pack2(x0, x1, a1h[ktw][pos],     a1l[ktw][pos]);
            split_pack2(x2, x3, a1h[ktw][pos + 1], a1l[ktw][pos + 1]);
        }

        // ---- layer 1b + final dot ----
        float rA = 0.f, rB = 0.f;
        #pragma unroll
        for (int n = 0; n < 4; n++) {
            float c1[4] = {0.f, 0.f, 0.f, 0.f};
            #pragma unroll
            for (int kt = 0; kt < 2; kt++) {
                uint4 Bq = __ldg(B1bu + (n * 2 + kt) * 32 + lane);
                mma16816(c1, a1h[kt], Bq.x, Bq.y);
                mma16816(c1, a1l[kt], Bq.x, Bq.y);
                mma16816(c1, a1h[kt], Bq.z, Bq.w);
            }
            float2 bz = __ldg(b1f + n * 32 + lane);
            float y0 = fmaxf(c1[0] + bz.x, 0.f);
            float y1 = fmaxf(c1[1] + bz.y, 0.f);
            float y2 = fmaxf(c1[2] + bz.x, 0.f);
            float y3 = fmaxf(c1[3] + bz.y, 0.f);
            float4 w2 = __ldg(w2f + n * 32 + lane);
            rA = fmaf(w2.x, xv[n][0], rA); rA = fmaf(w2.y, xv[n][1], rA);
            rA = fmaf(w2.z, y0, rA);       rA = fmaf(w2.w, y1, rA);
            rB = fmaf(w2.x, xv[n][2], rB); rB = fmaf(w2.y, xv[n][3], rB);
            rB = fmaf(w2.z, y2, rB);       rB = fmaf(w2.w, y3, rB);
        }
        rA += __shfl_xor_sync(0xFFFFFFFFu, rA, 1);
        rA += __shfl_xor_sync(0xFFFFFFFFu, rA, 2);
        rB += __shfl_xor_sync(0xFFFFFFFFu, rB, 1);
        rB += __shfl_xor_sync(0xFFFFFFFFu, rB, 2);
        if (qp == 0) {
            long long rowA = cbase + rbase + mi * 16 + q;
            long long rowB = rowA + 8;
            if (rowA < (long long)Btot) out[rowA] = rA + b2v;
            if (rowB < (long long)Btot) out[rowB] = rB + b2v;
        }
    }
}

// ======================= launch =======================
extern "C" void kernel_launch(void* const* d_in, const int* in_sizes, int n_in,
                              void* d_out, int out_size) {
    const float* pov   = (const float*)d_in[0];
    const float* white = (const float*)d_in[1];
    const float* black = (const float*)d_in[2];
    const float* Ww = (const float*)d_in[3];
    const float* bw = (const float*)d_in[4];
    const float* Wb = (const float*)d_in[5];
    const float* bb = (const float*)d_in[6];
    const float* W0 = (const float*)d_in[7];
    const float* b0 = (const float*)d_in[8];
    const float* W1 = (const float*)d_in[9];
    const float* b1 = (const float*)d_in[10];
    const float* W2 = (const float*)d_in[11];
    const float* b2 = (const float*)d_in[12];
    const int B = in_sizes[0];

    prep_kernel<<<1, 256>>>(Ww, Wb, W0, W1, bw, bb, b0, b1, W2, b2);

    const int smem_bytes = SMEM_WORDS * 4;   // 57856 B
    cudaFuncSetAttribute(nnue_main, cudaFuncAttributeMaxDynamicSharedMemorySize, smem_bytes);
    int grid = (B + 127) >> 7;
    nnue_main<<<grid, 128, smem_bytes>>>(pov, white, black, (float*)d_out, B);
}

// round 6
// speedup vs baseline: 3.4388x; 3.4388x over previous
#include <cuda_runtime.h>
#include <cuda_bf16.h>
#include <stdint.h>

// ======================= fragment-packed weight image =======================
#define OFF_B1    0
#define OFF_B0    28672
#define OFF_B1B   36864
#define OFF_BIAS1 40960
#define OFF_B0F   43008
#define OFF_B1F   44032
#define OFF_W2F   45056
#define OFF_B2    47104
#define PACK_BYTES 47120

__device__ __align__(16) unsigned char g_pack[PACK_BYTES];

// ======================= helpers =======================
__device__ __forceinline__ uint32_t pack_bf16x2(float a, float b) {
    __nv_bfloat16 ha = __float2bfloat16(a), hb = __float2bfloat16(b);
    return (uint32_t)__bfloat16_as_ushort(ha) | ((uint32_t)__bfloat16_as_ushort(hb) << 16);
}
__device__ __forceinline__ void bsplit(float f, float& h, float& l) {
    __nv_bfloat16 hb = __float2bfloat16(f);
    h = __bfloat162float(hb);
    l = f - h;
}
__device__ __forceinline__ void split_pack2(float f0, float f1, uint32_t& hr, uint32_t& lr) {
    float h0, l0, h1, l1;
    bsplit(f0, h0, l0);
    bsplit(f1, h1, l1);
    hr = pack_bf16x2(h0, h1);
    lr = pack_bf16x2(l0, l1);
}
__device__ __forceinline__ void mma16816(float* c, const uint32_t* a, uint32_t b0, uint32_t b1) {
    asm volatile(
        "mma.sync.aligned.m16n8k16.row.col.f32.bf16.bf16.f32 "
        "{%0,%1,%2,%3}, {%4,%5,%6,%7}, {%8,%9}, {%0,%1,%2,%3};"
        : "+f"(c[0]), "+f"(c[1]), "+f"(c[2]), "+f"(c[3])
        : "r"(a[0]), "r"(a[1]), "r"(a[2]), "r"(a[3]), "r"(b0), "r"(b1));
}

// ======================= prep kernel =======================
__device__ __forceinline__ float getW1c(const float* Ww, const float* Wb, int n, int k) {
    if (k >= 98) return 0.f;
    if (n < 32) return Ww[n * 98 + k];
    int kk = k + 49; if (kk >= 98) kk -= 98;
    return Wb[(n - 32) * 98 + kk];
}

__global__ void prep_kernel(const float* __restrict__ Ww, const float* __restrict__ Wb,
                            const float* __restrict__ W0, const float* __restrict__ W1,
                            const float* __restrict__ bw, const float* __restrict__ bb,
                            const float* __restrict__ b0, const float* __restrict__ b1,
                            const float* __restrict__ W2, const float* __restrict__ b2)
{
    const int tid = threadIdx.x;  // 256 threads
    char* gp = (char*)g_pack;

    for (int idx = tid; idx < 8 * 7 * 32; idx += 256) {
        int lane = idx & 31, t = idx >> 5;
        int kt = t % 7, nt = t / 7;
        int n = nt * 8 + (lane >> 2);
        int k0 = kt * 16 + (lane & 3) * 2;
        float w[4] = { getW1c(Ww, Wb, n, k0),     getW1c(Ww, Wb, n, k0 + 1),
                       getW1c(Ww, Wb, n, k0 + 8), getW1c(Ww, Wb, n, k0 + 9) };
        float h[4], l[4];
        for (int i = 0; i < 4; i++) bsplit(w[i], h[i], l[i]);
        uint4 v;
        v.x = pack_bf16x2(h[0], h[1]); v.y = pack_bf16x2(h[2], h[3]);
        v.z = pack_bf16x2(l[0], l[1]); v.w = pack_bf16x2(l[2], l[3]);
        ((uint4*)(gp + OFF_B1))[idx] = v;
    }
    for (int idx = tid; idx < 4 * 4 * 32; idx += 256) {
        int lane = idx & 31, t = idx >> 5;
        int kt = t & 3, nt = t >> 2;
        int n = nt * 8 + (lane >> 2);
        int k0 = kt * 16 + (lane & 3) * 2;
        float w[4] = { W0[n * 64 + k0],     W0[n * 64 + k0 + 1],
                       W0[n * 64 + k0 + 8], W0[n * 64 + k0 + 9] };
        float h[4], l[4];
        for (int i = 0; i < 4; i++) bsplit(w[i], h[i], l[i]);
        uint4 v;
        v.x = pack_bf16x2(h[0], h[1]); v.y = pack_bf16x2(h[2], h[3]);
        v.z = pack_bf16x2(l[0], l[1]); v.w = pack_bf16x2(l[2], l[3]);
        ((uint4*)(gp + OFF_B0))[idx] = v;
    }
    for (int idx = tid; idx < 4 * 2 * 32; idx += 256) {
        int lane = idx & 31, t = idx >> 5;
        int kt = t & 1, nt = t >> 1;
        int n = nt * 8 + (lane >> 2);
        int k0 = kt * 16 + (lane & 3) * 2;
        float w[4] = { W1[n * 32 + k0],     W1[n * 32 + k0 + 1],
                       W1[n * 32 + k0 + 8], W1[n * 32 + k0 + 9] };
        float h[4], l[4];
        for (int i = 0; i < 4; i++) bsplit(w[i], h[i], l[i]);
        uint4 v;
        v.x = pack_bf16x2(h[0], h[1]); v.y = pack_bf16x2(h[2], h[3]);
        v.z = pack_bf16x2(l[0], l[1]); v.w = pack_bf16x2(l[2], l[3]);
        ((uint4*)(gp + OFF_B1B))[idx] = v;
    }
    for (int idx = tid; idx < 4 * 32; idx += 256) {
        int lane = idx & 31, j = idx >> 5;
        int c = j * 8 + (lane & 3) * 2;
        float4 bf; bf.x = bw[c]; bf.y = bw[c + 1]; bf.z = bb[c]; bf.w = bb[c + 1];
        ((float4*)(gp + OFF_BIAS1))[idx] = bf;
        float2 f0; f0.x = b0[c]; f0.y = b0[c + 1];
        ((float2*)(gp + OFF_B0F))[idx] = f0;
        float2 f1; f1.x = b1[c]; f1.y = b1[c + 1];
        ((float2*)(gp + OFF_B1F))[idx] = f1;
        float4 w2; w2.x = W2[c]; w2.y = W2[c + 1]; w2.z = W2[32 + c]; w2.w = W2[32 + c + 1];
        ((float4*)(gp + OFF_W2F))[idx] = w2;
    }
    if (tid == 0) *((float*)(gp + OFF_B2)) = b2[0];
}

// ======================= main fused kernel =======================
// dyn smem: [pack 47120 B][st 128*104 f32][spov 128 f32]
#define ST_STRIDE 104
#define SMEM_BYTES (PACK_BYTES + 128 * ST_STRIDE * 4 + 512)   // 100880 B

__global__ void __launch_bounds__(128, 2)
nnue_main(const float* __restrict__ pov, const float* __restrict__ white,
          const float* __restrict__ black, float* __restrict__ out, int Btot)
{
    extern __shared__ __align__(16) unsigned char smem[];
    unsigned char* packS = smem;
    float* st   = (float*)(smem + PACK_BYTES);
    float* spov = st + 128 * ST_STRIDE;

    const int tid  = threadIdx.x;
    const int warp = tid >> 5;
    const int lane = tid & 31;
    const int q    = lane >> 2;
    const int qp   = lane & 3;
    const long long cbase = (long long)blockIdx.x * 128;

    // ---- copy weight pack into smem ----
    {
        const uint4* src = (const uint4*)g_pack;
        uint4* dst = (uint4*)packS;
        #pragma unroll 4
        for (int i = tid; i < PACK_BYTES / 16; i += 128) dst[i] = src[i];
    }

    // ---- zero pad cols 98..103 ----
    #pragma unroll
    for (int c = 98; c < 104; c++) st[tid * ST_STRIDE + c] = 0.f;

    // ---- stage inputs (coalesced float4) ----
    if (cbase + 128 <= (long long)Btot) {
        const float4* gw = (const float4*)(white + cbase * 49);
        const float4* gb = (const float4*)(black + cbase * 49);
        #pragma unroll 4
        for (int i = tid; i < 1568; i += 128) {
            float4 v = gw[i];
            int g = 4 * i;
            #pragma unroll
            for (int e = 0; e < 4; e++) {
                int gg = g + e;
                int s = gg / 49, c = gg - s * 49;
                float val = (e == 0) ? v.x : (e == 1) ? v.y : (e == 2) ? v.z : v.w;
                st[s * ST_STRIDE + c] = val;
            }
            float4 u = gb[i];
            #pragma unroll
            for (int e = 0; e < 4; e++) {
                int gg = g + e;
                int s = gg / 49, c = gg - s * 49;
                float val = (e == 0) ? u.x : (e == 1) ? u.y : (e == 2) ? u.z : u.w;
                st[s * ST_STRIDE + 49 + c] = val;
            }
        }
        spov[tid] = pov[cbase + tid];
    } else {
        for (int i = tid; i < 6272; i += 128) {
            int s = i / 49, c = i - s * 49;
            long long row = cbase + s;
            bool ok = row < (long long)Btot;
            st[s * ST_STRIDE + c]      = ok ? white[row * 49 + c] : 0.f;
            st[s * ST_STRIDE + 49 + c] = ok ? black[row * 49 + c] : 0.f;
        }
        spov[tid] = (cbase + tid < (long long)Btot) ? pov[cbase + tid] : 0.f;
    }
    __syncthreads();

    const uint4*  B1u  = (const uint4*)(packS + OFF_B1);
    const uint4*  B0u  = (const uint4*)(packS + OFF_B0);
    const uint4*  B1bu = (const uint4*)(packS + OFF_B1B);
    const float4* bia1 = (const float4*)(packS + OFF_BIAS1);
    const float2* b0f  = (const float2*)(packS + OFF_B0F);
    const float2* b1f  = (const float2*)(packS + OFF_B1F);
    const float4* w2f  = (const float4*)(packS + OFF_W2F);
    const float   b2v  = *((const float*)(packS + OFF_B2));

    const int rbase = warp * 32;
    // row bases for the 4 row-groups (2 tiles x 2 half-tiles)
    const float* r00 = st + (rbase + q)      * ST_STRIDE;
    const float* r01 = st + (rbase + q + 8)  * ST_STRIDE;
    const float* r10 = st + (rbase + q + 16) * ST_STRIDE;
    const float* r11 = st + (rbase + q + 24) * ST_STRIDE;

    // ================= layer 1: both m-tiles share every B fragment =================
    float cw[4][2][4], cb[4][2][4];
    #pragma unroll
    for (int j = 0; j < 4; j++)
        #pragma unroll
        for (int mi = 0; mi < 2; mi++)
            #pragma unroll
            for (int i = 0; i < 4; i++) { cw[j][mi][i] = 0.f; cb[j][mi][i] = 0.f; }

    #pragma unroll
    for (int kt = 0; kt < 7; kt++) {
        const int c0 = kt * 16 + qp * 2;
        uint32_t ah[2][4], al[2][4];
        {
            float2 p;
            p = *(const float2*)(r00 + c0); split_pack2(p.x, p.y, ah[0][0], al[0][0]);
            p = *(const float2*)(r01 + c0); split_pack2(p.x, p.y, ah[0][1], al[0][1]);
            p = *(const float2*)(r10 + c0); split_pack2(p.x, p.y, ah[1][0], al[1][0]);
            p = *(const float2*)(r11 + c0); split_pack2(p.x, p.y, ah[1][1], al[1][1]);
            if (kt < 6) {
                p = *(const float2*)(r00 + c0 + 8); split_pack2(p.x, p.y, ah[0][2], al[0][2]);
                p = *(const float2*)(r01 + c0 + 8); split_pack2(p.x, p.y, ah[0][3], al[0][3]);
                p = *(const float2*)(r10 + c0 + 8); split_pack2(p.x, p.y, ah[1][2], al[1][2]);
                p = *(const float2*)(r11 + c0 + 8); split_pack2(p.x, p.y, ah[1][3], al[1][3]);
            } else {
                ah[0][2] = al[0][2] = ah[0][3] = al[0][3] = 0u;
                ah[1][2] = al[1][2] = ah[1][3] = al[1][3] = 0u;
            }
        }
        #pragma unroll
        for (int j = 0; j < 4; j++) {
            uint4 Bw = B1u[(j * 7 + kt) * 32 + lane];
            uint4 Bb = B1u[((j + 4) * 7 + kt) * 32 + lane];
            #pragma unroll
            for (int mi = 0; mi < 2; mi++) {
                mma16816(cw[j][mi], ah[mi], Bw.x, Bw.y);
                mma16816(cw[j][mi], al[mi], Bw.x, Bw.y);
                mma16816(cw[j][mi], ah[mi], Bw.z, Bw.w);
                mma16816(cb[j][mi], ah[mi], Bb.x, Bb.y);
                mma16816(cb[j][mi], al[mi], Bb.x, Bb.y);
                mma16816(cb[j][mi], ah[mi], Bb.z, Bb.w);
            }
        }
    }

    // ================= per-tile tail (sequential: keeps registers low) =================
    #pragma unroll
    for (int mi = 0; mi < 2; mi++) {
        float pv0 = spov[rbase + mi * 16 + q];
        float pv1 = spov[rbase + mi * 16 + q + 8];
        float pm0 = 1.f - pv0, pm1 = 1.f - pv1;

        // ---- epilogue 1: bias + pov mix + relu -> layer-0 A frags ----
        uint32_t a0h[4][4], a0l[4][4];
        #pragma unroll
        for (int j = 0; j < 4; j++) {
            float4 bi = bia1[j * 32 + lane];
            float w0 = cw[j][mi][0] + bi.x, w1 = cw[j][mi][1] + bi.y;
            float w2_ = cw[j][mi][2] + bi.x, w3 = cw[j][mi][3] + bi.y;
            float bb0 = cb[j][mi][0] + bi.z, bb1 = cb[j][mi][1] + bi.w;
            float bb2 = cb[j][mi][2] + bi.z, bb3 = cb[j][mi][3] + bi.w;
            float vA0 = fmaxf(fmaf(pv0, w0, pm0 * bb0), 0.f);
            float vA1 = fmaxf(fmaf(pv0, w1, pm0 * bb1), 0.f);
            float vA2 = fmaxf(fmaf(pv1, w2_, pm1 * bb2), 0.f);
            float vA3 = fmaxf(fmaf(pv1, w3, pm1 * bb3), 0.f);
            float vB0 = fmaxf(fmaf(pv0, bb0, pm0 * w0), 0.f);
            float vB1 = fmaxf(fmaf(pv0, bb1, pm0 * w1), 0.f);
            float vB2 = fmaxf(fmaf(pv1, bb2, pm1 * w2_), 0.f);
            float vB3 = fmaxf(fmaf(pv1, bb3, pm1 * w3), 0.f);
            int ktw = j >> 1;
            int pos = (j & 1) ? 2 : 0;
            split_pack2(vA0, vA1, a0h[ktw][pos],     a0l[ktw][pos]);
            split_pack2(vA2, vA3, a0h[ktw][pos + 1], a0l[ktw][pos + 1]);
            split_pack2(vB0, vB1, a0h[ktw + 2][pos],     a0l[ktw + 2][pos]);
            split_pack2(vB2, vB3, a0h[ktw + 2][pos + 1], a0l[ktw + 2][pos + 1]);
        }

        // ---- layer 0 ----
        float xv[4][4];
        uint32_t a1h[2][4], a1l[2][4];
        #pragma unroll
        for (int n = 0; n < 4; n++) {
            float c0[4] = {0.f, 0.f, 0.f, 0.f};
            #pragma unroll
            for (int kt = 0; kt < 4; kt++) {
                uint4 Bq = B0u[(n * 4 + kt) * 32 + lane];
                mma16816(c0, a0h[kt], Bq.x, Bq.y);
                mma16816(c0, a0l[kt], Bq.x, Bq.y);
                mma16816(c0, a0h[kt], Bq.z, Bq.w);
            }
            float2 bz = b0f[n * 32 + lane];
            float x0 = fmaxf(c0[0] + bz.x, 0.f);
            float x1 = fmaxf(c0[1] + bz.y, 0.f);
            float x2 = fmaxf(c0[2] + bz.x, 0.f);
            float x3 = fmaxf(c0[3] + bz.y, 0.f);
            xv[n][0] = x0; xv[n][1] = x1; xv[n][2] = x2; xv[n][3] = x3;
            int ktw = n >> 1;
            int pos = (n & 1) ? 2 : 0;
            split_pack2(x0, x1, a1h[ktw][pos],     a1l[ktw][pos]);
            split_pack2(x2, x3, a1h[ktw][pos + 1], a1l[ktw][pos + 1]);
        }

        // ---- layer 1b + final dot ----
        float rA = 0.f, rB = 0.f;
        #pragma unroll
        for (int n = 0; n < 4; n++) {
            float c1[4] = {0.f, 0.f, 0.f, 0.f};
            #pragma unroll
            for (int kt = 0; kt < 2; kt++) {
                uint4 Bq = B1bu[(n * 2 + kt) * 32 + lane];
                mma16816(c1, a1h[kt], Bq.x, Bq.y);
                mma16816(c1, a1l[kt], Bq.x, Bq.y);
                mma16816(c1, a1h[kt], Bq.z, Bq.w);
            }
            float2 bz = b1f[n * 32 + lane];
            float y0 = fmaxf(c1[0] + bz.x, 0.f);
            float y1 = fmaxf(c1[1] + bz.y, 0.f);
            float y2 = fmaxf(c1[2] + bz.x, 0.f);
            float y3 = fmaxf(c1[3] + bz.y, 0.f);
            float4 w2 = w2f[n * 32 + lane];
            rA = fmaf(w2.x, xv[n][0], rA); rA = fmaf(w2.y, xv[n][1], rA);
            rA = fmaf(w2.z, y0, rA);       rA = fmaf(w2.w, y1, rA);
            rB = fmaf(w2.x, xv[n][2], rB); rB = fmaf(w2.y, xv[n][3], rB);
            rB = fmaf(w2.z, y2, rB);       rB = fmaf(w2.w, y3, rB);
        }
        rA += __shfl_xor_sync(0xFFFFFFFFu, rA, 1);
        rA += __shfl_xor_sync(0xFFFFFFFFu, rA, 2);
        rB += __shfl_xor_sync(0xFFFFFFFFu, rB, 1);
        rB += __shfl_xor_sync(0xFFFFFFFFu, rB, 2);
        if (qp == 0) {
            long long rowA = cbase + rbase + mi * 16 + q;
            long long rowB = rowA + 8;
            if (rowA < (long long)Btot) out[rowA] = rA + b2v;
            if (rowB < (long long)Btot) out[rowB] = rB + b2v;
        }
    }
}

// ======================= launch =======================
extern "C" void kernel_launch(void* const* d_in, const int* in_sizes, int n_in,
                              void* d_out, int out_size) {
    const float* pov   = (const float*)d_in[0];
    const float* white = (const float*)d_in[1];
    const float* black = (const float*)d_in[2];
    const float* Ww = (const float*)d_in[3];
    const float* bw = (const float*)d_in[4];
    const float* Wb = (const float*)d_in[5];
    const float* bb = (const float*)d_in[6];
    const float* W0 = (const float*)d_in[7];
    const float* b0 = (const float*)d_in[8];
    const float* W1 = (const float*)d_in[9];
    const float* b1 = (const float*)d_in[10];
    const float* W2 = (const float*)d_in[11];
    const float* b2 = (const float*)d_in[12];
    const int B = in_sizes[0];

    prep_kernel<<<1, 256>>>(Ww, Wb, W0, W1, bw, bb, b0, b1, W2, b2);

    cudaFuncSetAttribute(nnue_main, cudaFuncAttributeMaxDynamicSharedMemorySize, SMEM_BYTES);
    int grid = (B + 127) >> 7;
    nnue_main<<<grid, 128, SMEM_BYTES>>>(pov, white, black, (float*)d_out, B);
}

// round 7
// speedup vs baseline: 3.6200x; 1.0527x over previous
#include <cuda_runtime.h>
#include <cuda_bf16.h>
#include <stdint.h>

// ======================= fragment-packed weight image =======================
#define OFF_B1    0
#define OFF_B0    28672
#define OFF_B1B   36864
#define OFF_BIAS1 40960
#define OFF_B0F   43008
#define OFF_B1F   44032
#define OFF_W2F   45056
#define OFF_B2    47104
#define PACK_BYTES 47120

__device__ __align__(16) unsigned char g_pack[PACK_BYTES];

// ======================= helpers =======================
__device__ __forceinline__ uint32_t pack_bf16x2(float a, float b) {
    __nv_bfloat16 ha = __float2bfloat16(a), hb = __float2bfloat16(b);
    return (uint32_t)__bfloat16_as_ushort(ha) | ((uint32_t)__bfloat16_as_ushort(hb) << 16);
}
__device__ __forceinline__ void bsplit(float f, float& h, float& l) {
    __nv_bfloat16 hb = __float2bfloat16(f);
    h = __bfloat162float(hb);
    l = f - h;
}
__device__ __forceinline__ void split_pack2(float f0, float f1, uint32_t& hr, uint32_t& lr) {
    float h0, l0, h1, l1;
    bsplit(f0, h0, l0);
    bsplit(f1, h1, l1);
    hr = pack_bf16x2(h0, h1);
    lr = pack_bf16x2(l0, l1);
}
__device__ __forceinline__ void mma16816(float* c, const uint32_t* a, uint32_t b0, uint32_t b1) {
    asm volatile(
        "mma.sync.aligned.m16n8k16.row.col.f32.bf16.bf16.f32 "
        "{%0,%1,%2,%3}, {%4,%5,%6,%7}, {%8,%9}, {%0,%1,%2,%3};"
        : "+f"(c[0]), "+f"(c[1]), "+f"(c[2]), "+f"(c[3])
        : "r"(a[0]), "r"(a[1]), "r"(a[2]), "r"(a[3]), "r"(b0), "r"(b1));
}

// ======================= prep kernel =======================
__device__ __forceinline__ float getW1c(const float* Ww, const float* Wb, int n, int k) {
    if (k >= 98) return 0.f;
    if (n < 32) return Ww[n * 98 + k];
    int kk = k + 49; if (kk >= 98) kk -= 98;
    return Wb[(n - 32) * 98 + kk];
}

__global__ void prep_kernel(const float* __restrict__ Ww, const float* __restrict__ Wb,
                            const float* __restrict__ W0, const float* __restrict__ W1,
                            const float* __restrict__ bw, const float* __restrict__ bb,
                            const float* __restrict__ b0, const float* __restrict__ b1,
                            const float* __restrict__ W2, const float* __restrict__ b2)
{
    const int tid = threadIdx.x;  // 256 threads
    char* gp = (char*)g_pack;

    for (int idx = tid; idx < 8 * 7 * 32; idx += 256) {
        int lane = idx & 31, t = idx >> 5;
        int kt = t % 7, nt = t / 7;
        int n = nt * 8 + (lane >> 2);
        int k0 = kt * 16 + (lane & 3) * 2;
        float w[4] = { getW1c(Ww, Wb, n, k0),     getW1c(Ww, Wb, n, k0 + 1),
                       getW1c(Ww, Wb, n, k0 + 8), getW1c(Ww, Wb, n, k0 + 9) };
        float h[4], l[4];
        for (int i = 0; i < 4; i++) bsplit(w[i], h[i], l[i]);
        uint4 v;
        v.x = pack_bf16x2(h[0], h[1]); v.y = pack_bf16x2(h[2], h[3]);
        v.z = pack_bf16x2(l[0], l[1]); v.w = pack_bf16x2(l[2], l[3]);
        ((uint4*)(gp + OFF_B1))[idx] = v;
    }
    for (int idx = tid; idx < 4 * 4 * 32; idx += 256) {
        int lane = idx & 31, t = idx >> 5;
        int kt = t & 3, nt = t >> 2;
        int n = nt * 8 + (lane >> 2);
        int k0 = kt * 16 + (lane & 3) * 2;
        float w[4] = { W0[n * 64 + k0],     W0[n * 64 + k0 + 1],
                       W0[n * 64 + k0 + 8], W0[n * 64 + k0 + 9] };
        float h[4], l[4];
        for (int i = 0; i < 4; i++) bsplit(w[i], h[i], l[i]);
        uint4 v;
        v.x = pack_bf16x2(h[0], h[1]); v.y = pack_bf16x2(h[2], h[3]);
        v.z = pack_bf16x2(l[0], l[1]); v.w = pack_bf16x2(l[2], l[3]);
        ((uint4*)(gp + OFF_B0))[idx] = v;
    }
    for (int idx = tid; idx < 4 * 2 * 32; idx += 256) {
        int lane = idx & 31, t = idx >> 5;
        int kt = t & 1, nt = t >> 1;
        int n = nt * 8 + (lane >> 2);
        int k0 = kt * 16 + (lane & 3) * 2;
        float w[4] = { W1[n * 32 + k0],     W1[n * 32 + k0 + 1],
                       W1[n * 32 + k0 + 8], W1[n * 32 + k0 + 9] };
        float h[4], l[4];
        for (int i = 0; i < 4; i++) bsplit(w[i], h[i], l[i]);
        uint4 v;
        v.x = pack_bf16x2(h[0], h[1]); v.y = pack_bf16x2(h[2], h[3]);
        v.z = pack_bf16x2(l[0], l[1]); v.w = pack_bf16x2(l[2], l[3]);
        ((uint4*)(gp + OFF_B1B))[idx] = v;
    }
    for (int idx = tid; idx < 4 * 32; idx += 256) {
        int lane = idx & 31, j = idx >> 5;
        int c = j * 8 + (lane & 3) * 2;
        float4 bf; bf.x = bw[c]; bf.y = bw[c + 1]; bf.z = bb[c]; bf.w = bb[c + 1];
        ((float4*)(gp + OFF_BIAS1))[idx] = bf;
        float2 f0; f0.x = b0[c]; f0.y = b0[c + 1];
        ((float2*)(gp + OFF_B0F))[idx] = f0;
        float2 f1; f1.x = b1[c]; f1.y = b1[c + 1];
        ((float2*)(gp + OFF_B1F))[idx] = f1;
        float4 w2; w2.x = W2[c]; w2.y = W2[c + 1]; w2.z = W2[32 + c]; w2.w = W2[32 + c + 1];
        ((float4*)(gp + OFF_W2F))[idx] = w2;
    }
    if (tid == 0) *((float*)(gp + OFF_B2)) = b2[0];
}

// ======================= main fused kernel =======================
// dyn smem: [pack 47120 B][st 64*104 f32 = 26624 B][spov 128 f32]
// 2-pass staging: 64 rows per pass -> 74256 B total -> 3 CTAs/SM
#define ST_STRIDE 104
#define STAGE_ROWS 64
#define SMEM_BYTES (PACK_BYTES + STAGE_ROWS * ST_STRIDE * 4 + 512)

__global__ void __launch_bounds__(128, 3)
nnue_main(const float* __restrict__ pov, const float* __restrict__ white,
          const float* __restrict__ black, float* __restrict__ out, int Btot)
{
    extern __shared__ __align__(16) unsigned char smem[];
    unsigned char* packS = smem;
    float* st   = (float*)(smem + PACK_BYTES);
    float* spov = st + STAGE_ROWS * ST_STRIDE;

    const int tid  = threadIdx.x;
    const int warp = tid >> 5;
    const int lane = tid & 31;
    const int q    = lane >> 2;
    const int qp   = lane & 3;
    const long long cbase = (long long)blockIdx.x * 128;

    // ---- copy weight pack into smem (once) ----
    {
        const uint4* src = (const uint4*)g_pack;
        uint4* dst = (uint4*)packS;
        #pragma unroll 4
        for (int i = tid; i < PACK_BYTES / 16; i += 128) dst[i] = src[i];
    }
    // ---- pov for all 128 rows ----
    spov[tid] = (cbase + tid < (long long)Btot) ? pov[cbase + tid] : 0.f;

    const uint4*  B1u  = (const uint4*)(packS + OFF_B1);
    const uint4*  B0u  = (const uint4*)(packS + OFF_B0);
    const uint4*  B1bu = (const uint4*)(packS + OFF_B1B);
    const float4* bia1 = (const float4*)(packS + OFF_BIAS1);
    const float2* b0f  = (const float2*)(packS + OFF_B0F);
    const float2* b1f  = (const float2*)(packS + OFF_B1F);
    const float4* w2f  = (const float4*)(packS + OFF_W2F);

    #pragma unroll 1
    for (int pass = 0; pass < 2; pass++) {
        const long long pbase = cbase + pass * STAGE_ROWS;
        if (pass > 0) __syncthreads();   // previous pass reads complete

        // ---- zero pad cols 98..103 (rows 0..63) ----
        if (tid < STAGE_ROWS) {
            #pragma unroll
            for (int c = 98; c < 104; c++) st[tid * ST_STRIDE + c] = 0.f;
        }

        // ---- stage 64 rows (coalesced float4) ----
        if (pbase + STAGE_ROWS <= (long long)Btot) {
            const float4* gw = (const float4*)(white + pbase * 49);
            const float4* gb = (const float4*)(black + pbase * 49);
            #pragma unroll 2
            for (int i = tid; i < 784; i += 128) {   // 64*49/4
                float4 v = gw[i];
                int g = 4 * i;
                #pragma unroll
                for (int e = 0; e < 4; e++) {
                    int gg = g + e;
                    int s = gg / 49, c = gg - s * 49;
                    float val = (e == 0) ? v.x : (e == 1) ? v.y : (e == 2) ? v.z : v.w;
                    st[s * ST_STRIDE + c] = val;
                }
                float4 u = gb[i];
                #pragma unroll
                for (int e = 0; e < 4; e++) {
                    int gg = g + e;
                    int s = gg / 49, c = gg - s * 49;
                    float val = (e == 0) ? u.x : (e == 1) ? u.y : (e == 2) ? u.z : u.w;
                    st[s * ST_STRIDE + 49 + c] = val;
                }
            }
        } else {
            for (int i = tid; i < STAGE_ROWS * 49; i += 128) {
                int s = i / 49, c = i - s * 49;
                long long row = pbase + s;
                bool ok = row < (long long)Btot;
                st[s * ST_STRIDE + c]      = ok ? white[row * 49 + c] : 0.f;
                st[s * ST_STRIDE + 49 + c] = ok ? black[row * 49 + c] : 0.f;
            }
        }
        __syncthreads();

        // ---- this warp's m16 tile: local rows warp*16 + q, + 8 ----
        const float* r0 = st + (warp * 16 + q) * ST_STRIDE;
        const float* r1 = r0 + 8 * ST_STRIDE;

        // ================= layer 1 =================
        float cw[4][4], cb[4][4];
        #pragma unroll
        for (int j = 0; j < 4; j++)
            #pragma unroll
            for (int i = 0; i < 4; i++) { cw[j][i] = 0.f; cb[j][i] = 0.f; }

        #pragma unroll
        for (int kt = 0; kt < 7; kt++) {
            const int c0 = kt * 16 + qp * 2;
            uint32_t ah[4], al[4];
            float2 p;
            p = *(const float2*)(r0 + c0); split_pack2(p.x, p.y, ah[0], al[0]);
            p = *(const float2*)(r1 + c0); split_pack2(p.x, p.y, ah[1], al[1]);
            if (kt < 6) {
                p = *(const float2*)(r0 + c0 + 8); split_pack2(p.x, p.y, ah[2], al[2]);
                p = *(const float2*)(r1 + c0 + 8); split_pack2(p.x, p.y, ah[3], al[3]);
            } else {
                ah[2] = al[2] = ah[3] = al[3] = 0u;
            }
            #pragma unroll
            for (int j = 0; j < 4; j++) {
                uint4 Bw = B1u[(j * 7 + kt) * 32 + lane];
                uint4 Bb = B1u[((j + 4) * 7 + kt) * 32 + lane];
                mma16816(cw[j], ah, Bw.x, Bw.y);
                mma16816(cw[j], al, Bw.x, Bw.y);
                mma16816(cw[j], ah, Bw.z, Bw.w);
                mma16816(cb[j], ah, Bb.x, Bb.y);
                mma16816(cb[j], al, Bb.x, Bb.y);
                mma16816(cb[j], ah, Bb.z, Bb.w);
            }
        }

        // ---- epilogue 1: bias + pov mix + relu -> layer-0 A frags ----
        const int prow = pass * STAGE_ROWS + warp * 16 + q;
        float pv0 = spov[prow];
        float pv1 = spov[prow + 8];
        float pm0 = 1.f - pv0, pm1 = 1.f - pv1;

        uint32_t a0h[4][4], a0l[4][4];
        #pragma unroll
        for (int j = 0; j < 4; j++) {
            float4 bi = bia1[j * 32 + lane];
            float w0 = cw[j][0] + bi.x, w1 = cw[j][1] + bi.y;
            float w2_ = cw[j][2] + bi.x, w3 = cw[j][3] + bi.y;
            float bb0 = cb[j][0] + bi.z, bb1 = cb[j][1] + bi.w;
            float bb2 = cb[j][2] + bi.z, bb3 = cb[j][3] + bi.w;
            float vA0 = fmaxf(fmaf(pv0, w0, pm0 * bb0), 0.f);
            float vA1 = fmaxf(fmaf(pv0, w1, pm0 * bb1), 0.f);
            float vA2 = fmaxf(fmaf(pv1, w2_, pm1 * bb2), 0.f);
            float vA3 = fmaxf(fmaf(pv1, w3, pm1 * bb3), 0.f);
            float vB0 = fmaxf(fmaf(pv0, bb0, pm0 * w0), 0.f);
            float vB1 = fmaxf(fmaf(pv0, bb1, pm0 * w1), 0.f);
            float vB2 = fmaxf(fmaf(pv1, bb2, pm1 * w2_), 0.f);
            float vB3 = fmaxf(fmaf(pv1, bb3, pm1 * w3), 0.f);
            int ktw = j >> 1;
            int pos = (j & 1) ? 2 : 0;
            split_pack2(vA0, vA1, a0h[ktw][pos],     a0l[ktw][pos]);
            split_pack2(vA2, vA3, a0h[ktw][pos + 1], a0l[ktw][pos + 1]);
            split_pack2(vB0, vB1, a0h[ktw + 2][pos],     a0l[ktw + 2][pos]);
            split_pack2(vB2, vB3, a0h[ktw + 2][pos + 1], a0l[ktw + 2][pos + 1]);
        }

        // ---- layer 0 ----
        float xv[4][4];
        uint32_t a1h[2][4], a1l[2][4];
        #pragma unroll
        for (int n = 0; n < 4; n++) {
            float c0v[4] = {0.f, 0.f, 0.f, 0.f};
            #pragma unroll
            for (int kt = 0; kt < 4; kt++) {
                uint4 Bq = B0u[(n * 4 + kt) * 32 + lane];
                mma16816(c0v, a0h[kt], Bq.x, Bq.y);
                mma16816(c0v, a0l[kt], Bq.x, Bq.y);
                mma16816(c0v, a0h[kt], Bq.z, Bq.w);
            }
            float2 bz = b0f[n * 32 + lane];
            float x0 = fmaxf(c0v[0] + bz.x, 0.f);
            float x1 = fmaxf(c0v[1] + bz.y, 0.f);
            float x2 = fmaxf(c0v[2] + bz.x, 0.f);
            float x3 = fmaxf(c0v[3] + bz.y, 0.f);
            xv[n][0] = x0; xv[n][1] = x1; xv[n][2] = x2; xv[n][3] = x3;
            int ktw = n >> 1;
            int pos = (n & 1) ? 2 : 0;
            split_pack2(x0, x1, a1h[ktw][pos],     a1l[ktw][pos]);
            split_pack2(x2, x3, a1h[ktw][pos + 1], a1l[ktw][pos + 1]);
        }

        // ---- layer 1b + final dot ----
        float rA = 0.f, rB = 0.f;
        #pragma unroll
        for (int n = 0; n < 4; n++) {
            float c1[4] = {0.f, 0.f, 0.f, 0.f};
            #pragma unroll
            for (int kt = 0; kt < 2; kt++) {
                uint4 Bq = B1bu[(n * 2 + kt) * 32 + lane];
                mma16816(c1, a1h[kt], Bq.x, Bq.y);
                mma16816(c1, a1l[kt], Bq.x, Bq.y);
                mma16816(c1, a1h[kt], Bq.z, Bq.w);
            }
            float2 bz = b1f[n * 32 + lane];
            float y0 = fmaxf(c1[0] + bz.x, 0.f);
            float y1 = fmaxf(c1[1] + bz.y, 0.f);
            float y2 = fmaxf(c1[2] + bz.x, 0.f);
            float y3 = fmaxf(c1[3] + bz.y, 0.f);
            float4 w2 = w2f[n * 32 + lane];
            rA = fmaf(w2.x, xv[n][0], rA); rA = fmaf(w2.y, xv[n][1], rA);
            rA = fmaf(w2.z, y0, rA);       rA = fmaf(w2.w, y1, rA);
            rB = fmaf(w2.x, xv[n][2], rB); rB = fmaf(w2.y, xv[n][3], rB);
            rB = fmaf(w2.z, y2, rB);       rB = fmaf(w2.w, y3, rB);
        }
        rA += __shfl_xor_sync(0xFFFFFFFFu, rA, 1);
        rA += __shfl_xor_sync(0xFFFFFFFFu, rA, 2);
        rB += __shfl_xor_sync(0xFFFFFFFFu, rB, 1);
        rB += __shfl_xor_sync(0xFFFFFFFFu, rB, 2);
        if (qp == 0) {
            const float b2v = *((const float*)(packS + OFF_B2));
            long long rowA = pbase + warp * 16 + q;
            long long rowB = rowA + 8;
            if (rowA < (long long)Btot) out[rowA] = rA + b2v;
            if (rowB < (long long)Btot) out[rowB] = rB + b2v;
        }
    }
}

// ======================= launch =======================
extern "C" void kernel_launch(void* const* d_in, const int* in_sizes, int n_in,
                              void* d_out, int out_size) {
    const float* pov   = (const float*)d_in[0];
    const float* white = (const float*)d_in[1];
    const float* black = (const float*)d_in[2];
    const float* Ww = (const float*)d_in[3];
    const float* bw = (const float*)d_in[4];
    const float* Wb = (const float*)d_in[5];
    const float* bb = (const float*)d_in[6];
    const float* W0 = (const float*)d_in[7];
    const float* b0 = (const float*)d_in[8];
    const float* W1 = (const float*)d_in[9];
    const float* b1 = (const float*)d_in[10];
    const float* W2 = (const float*)d_in[11];
    const float* b2 = (const float*)d_in[12];
    const int B = in_sizes[0];

    prep_kernel<<<1, 256>>>(Ww, Wb, W0, W1, bw, bb, b0, b1, W2, b2);

    cudaFuncSetAttribute(nnue_main, cudaFuncAttributeMaxDynamicSharedMemorySize, SMEM_BYTES);
    int grid = (B + 127) >> 7;
    nnue_main<<<grid, 128, SMEM_BYTES>>>(pov, white, black, (float*)d_out, B);
}

// round 8
// speedup vs baseline: 4.4887x; 1.2400x over previous
#include <cuda_runtime.h>
#include <cuda_bf16.h>
#include <stdint.h>

// ======================= fragment-packed weight image =======================
#define OFF_B1    0
#define OFF_B0    28672
#define OFF_B1B   36864
#define OFF_BIAS1 40960
#define OFF_B0F   43008
#define OFF_B1F   44032
#define OFF_W2F   45056
#define OFF_B2    47104
#define PACK_BYTES 47120

__device__ __align__(16) unsigned char g_pack[PACK_BYTES];

// ======================= helpers =======================
__device__ __forceinline__ uint32_t pack_bf16x2(float a, float b) {
    __nv_bfloat16 ha = __float2bfloat16(a), hb = __float2bfloat16(b);
    return (uint32_t)__bfloat16_as_ushort(ha) | ((uint32_t)__bfloat16_as_ushort(hb) << 16);
}
__device__ __forceinline__ void bsplit(float f, float& h, float& l) {
    __nv_bfloat16 hb = __float2bfloat16(f);
    h = __bfloat162float(hb);
    l = f - h;
}
// fast truncation split: hi = trunc-to-bf16 (exact residual), lo = rn-bf16 of residual
// hr = {bf16(f1_hi) : bf16(f0_hi)}, lr = {bf16(l1) : bf16(l0)}
__device__ __forceinline__ void split_pack2_fast(float f0, float f1, uint32_t& hr, uint32_t& lr) {
    uint32_t u0 = __float_as_uint(f0), u1 = __float_as_uint(f1);
    float h0 = __uint_as_float(u0 & 0xFFFF0000u);
    float h1 = __uint_as_float(u1 & 0xFFFF0000u);
    float l0 = f0 - h0;
    float l1 = f1 - h1;
    asm("prmt.b32 %0, %1, %2, 0x7632;" : "=r"(hr) : "r"(u0), "r"(u1));
    asm("cvt.rn.bf16x2.f32 %0, %1, %2;" : "=r"(lr) : "f"(l1), "f"(l0));
}
__device__ __forceinline__ void mma16816(float* c, const uint32_t* a, uint32_t b0, uint32_t b1) {
    asm volatile(
        "mma.sync.aligned.m16n8k16.row.col.f32.bf16.bf16.f32 "
        "{%0,%1,%2,%3}, {%4,%5,%6,%7}, {%8,%9}, {%0,%1,%2,%3};"
        : "+f"(c[0]), "+f"(c[1]), "+f"(c[2]), "+f"(c[3])
        : "r"(a[0]), "r"(a[1]), "r"(a[2]), "r"(a[3]), "r"(b0), "r"(b1));
}

// ======================= prep kernel =======================
__device__ __forceinline__ float getW1c(const float* Ww, const float* Wb, int n, int k) {
    if (k >= 98) return 0.f;
    if (n < 32) return Ww[n * 98 + k];
    int kk = k + 49; if (kk >= 98) kk -= 98;
    return Wb[(n - 32) * 98 + kk];
}

__global__ void prep_kernel(const float* __restrict__ Ww, const float* __restrict__ Wb,
                            const float* __restrict__ W0, const float* __restrict__ W1,
                            const float* __restrict__ bw, const float* __restrict__ bb,
                            const float* __restrict__ b0, const float* __restrict__ b1,
                            const float* __restrict__ W2, const float* __restrict__ b2)
{
    const int tid = threadIdx.x;  // 256 threads
    char* gp = (char*)g_pack;

    for (int idx = tid; idx < 8 * 7 * 32; idx += 256) {
        int lane = idx & 31, t = idx >> 5;
        int kt = t % 7, nt = t / 7;
        int n = nt * 8 + (lane >> 2);
        int k0 = kt * 16 + (lane & 3) * 2;
        float w[4] = { getW1c(Ww, Wb, n, k0),     getW1c(Ww, Wb, n, k0 + 1),
                       getW1c(Ww, Wb, n, k0 + 8), getW1c(Ww, Wb, n, k0 + 9) };
        float h[4], l[4];
        for (int i = 0; i < 4; i++) bsplit(w[i], h[i], l[i]);
        uint4 v;
        v.x = pack_bf16x2(h[0], h[1]); v.y = pack_bf16x2(h[2], h[3]);
        v.z = pack_bf16x2(l[0], l[1]); v.w = pack_bf16x2(l[2], l[3]);
        ((uint4*)(gp + OFF_B1))[idx] = v;
    }
    for (int idx = tid; idx < 4 * 4 * 32; idx += 256) {
        int lane = idx & 31, t = idx >> 5;
        int kt = t & 3, nt = t >> 2;
        int n = nt * 8 + (lane >> 2);
        int k0 = kt * 16 + (lane & 3) * 2;
        float w[4] = { W0[n * 64 + k0],     W0[n * 64 + k0 + 1],
                       W0[n * 64 + k0 + 8], W0[n * 64 + k0 + 9] };
        float h[4], l[4];
        for (int i = 0; i < 4; i++) bsplit(w[i], h[i], l[i]);
        uint4 v;
        v.x = pack_bf16x2(h[0], h[1]); v.y = pack_bf16x2(h[2], h[3]);
        v.z = pack_bf16x2(l[0], l[1]); v.w = pack_bf16x2(l[2], l[3]);
        ((uint4*)(gp + OFF_B0))[idx] = v;
    }
    for (int idx = tid; idx < 4 * 2 * 32; idx += 256) {
        int lane = idx & 31, t = idx >> 5;
        int kt = t & 1, nt = t >> 1;
        int n = nt * 8 + (lane >> 2);
        int k0 = kt * 16 + (lane & 3) * 2;
        float w[4] = { W1[n * 32 + k0],     W1[n * 32 + k0 + 1],
                       W1[n * 32 + k0 + 8], W1[n * 32 + k0 + 9] };
        float h[4], l[4];
        for (int i = 0; i < 4; i++) bsplit(w[i], h[i], l[i]);
        uint4 v;
        v.x = pack_bf16x2(h[0], h[1]); v.y = pack_bf16x2(h[2], h[3]);
        v.z = pack_bf16x2(l[0], l[1]); v.w = pack_bf16x2(l[2], l[3]);
        ((uint4*)(gp + OFF_B1B))[idx] = v;
    }
    for (int idx = tid; idx < 4 * 32; idx += 256) {
        int lane = idx & 31, j = idx >> 5;
        int c = j * 8 + (lane & 3) * 2;
        float4 bf; bf.x = bw[c]; bf.y = bw[c + 1]; bf.z = bb[c]; bf.w = bb[c + 1];
        ((float4*)(gp + OFF_BIAS1))[idx] = bf;
        float2 f0; f0.x = b0[c]; f0.y = b0[c + 1];
        ((float2*)(gp + OFF_B0F))[idx] = f0;
        float2 f1; f1.x = b1[c]; f1.y = b1[c + 1];
        ((float2*)(gp + OFF_B1F))[idx] = f1;
        float4 w2; w2.x = W2[c]; w2.y = W2[c + 1]; w2.z = W2[32 + c]; w2.w = W2[32 + c + 1];
        ((float4*)(gp + OFF_W2F))[idx] = w2;
    }
    if (tid == 0) *((float*)(gp + OFF_B2)) = b2[0];
}

// ======================= main fused kernel =======================
// 256 threads (8 warps) per CTA, 256 rows per CTA, 2 passes of 128 staged rows.
// dyn smem: [pack 47120][st 128*104 f32 = 53248][spov 256 f32 = 1024] = 101392 B -> 2 CTAs/SM
#define NT 256
#define ROWS_CTA 256
#define STAGE_ROWS 128
#define ST_STRIDE 104
#define SMEM_BYTES (PACK_BYTES + STAGE_ROWS * ST_STRIDE * 4 + ROWS_CTA * 4 + 16)

__global__ void __launch_bounds__(NT, 2)
nnue_main(const float* __restrict__ pov, const float* __restrict__ white,
          const float* __restrict__ black, float* __restrict__ out, int Btot)
{
    extern __shared__ __align__(16) unsigned char smem[];
    unsigned char* packS = smem;
    float* st   = (float*)(smem + PACK_BYTES);
    float* spov = st + STAGE_ROWS * ST_STRIDE;

    const int tid  = threadIdx.x;
    const int warp = tid >> 5;
    const int lane = tid & 31;
    const int q    = lane >> 2;
    const int qp   = lane & 3;
    const long long cbase = (long long)blockIdx.x * ROWS_CTA;

    // ---- copy weight pack into smem (once) ----
    {
        const uint4* src = (const uint4*)g_pack;
        uint4* dst = (uint4*)packS;
        #pragma unroll 4
        for (int i = tid; i < PACK_BYTES / 16; i += NT) dst[i] = src[i];
    }
    // ---- pov for all 256 rows ----
    spov[tid] = (cbase + tid < (long long)Btot) ? __ldcs(pov + cbase + tid) : 0.f;

    const uint4*  B1u  = (const uint4*)(packS + OFF_B1);
    const uint4*  B0u  = (const uint4*)(packS + OFF_B0);
    const uint4*  B1bu = (const uint4*)(packS + OFF_B1B);
    const float4* bia1 = (const float4*)(packS + OFF_BIAS1);
    const float2* b0f  = (const float2*)(packS + OFF_B0F);
    const float2* b1f  = (const float2*)(packS + OFF_B1F);
    const float4* w2f  = (const float4*)(packS + OFF_W2F);

    #pragma unroll 1
    for (int pass = 0; pass < 2; pass++) {
        const long long pbase = cbase + pass * STAGE_ROWS;
        if (pass > 0) __syncthreads();   // previous pass reads complete

        // ---- zero pad cols 98..103 (128 staged rows) ----
        if (tid < STAGE_ROWS) {
            #pragma unroll
            for (int c = 98; c < 104; c++) st[tid * ST_STRIDE + c] = 0.f;
        }

        // ---- stage 128 rows (coalesced float4, streaming) ----
        if (pbase + STAGE_ROWS <= (long long)Btot) {
            const float4* gw = (const float4*)(white + pbase * 49);
            const float4* gb = (const float4*)(black + pbase * 49);
            #pragma unroll 2
            for (int i = tid; i < 1568; i += NT) {   // 128*49/4
                float4 v = __ldcs(gw + i);
                int g = 4 * i;
                #pragma unroll
                for (int e = 0; e < 4; e++) {
                    int gg = g + e;
                    int s = gg / 49, c = gg - s * 49;
                    float val = (e == 0) ? v.x : (e == 1) ? v.y : (e == 2) ? v.z : v.w;
                    st[s * ST_STRIDE + c] = val;
                }
                float4 u = __ldcs(gb + i);
                #pragma unroll
                for (int e = 0; e < 4; e++) {
                    int gg = g + e;
                    int s = gg / 49, c = gg - s * 49;
                    float val = (e == 0) ? u.x : (e == 1) ? u.y : (e == 2) ? u.z : u.w;
                    st[s * ST_STRIDE + 49 + c] = val;
                }
            }
        } else {
            for (int i = tid; i < STAGE_ROWS * 49; i += NT) {
                int s = i / 49, c = i - s * 49;
                long long row = pbase + s;
                bool ok = row < (long long)Btot;
                st[s * ST_STRIDE + c]      = ok ? white[row * 49 + c] : 0.f;
                st[s * ST_STRIDE + 49 + c] = ok ? black[row * 49 + c] : 0.f;
            }
        }
        __syncthreads();

        // ---- this warp's m16 tile: local rows warp*16 + q, + 8 ----
        const float* r0 = st + (warp * 16 + q) * ST_STRIDE;
        const float* r1 = r0 + 8 * ST_STRIDE;

        // ================= layer 1 =================
        float cw[4][4], cb[4][4];
        #pragma unroll
        for (int j = 0; j < 4; j++)
            #pragma unroll
            for (int i = 0; i < 4; i++) { cw[j][i] = 0.f; cb[j][i] = 0.f; }

        #pragma unroll
        for (int kt = 0; kt < 7; kt++) {
            const int c0 = kt * 16 + qp * 2;
            uint32_t ah[4], al[4];
            float2 p;
            p = *(const float2*)(r0 + c0); split_pack2_fast(p.x, p.y, ah[0], al[0]);
            p = *(const float2*)(r1 + c0); split_pack2_fast(p.x, p.y, ah[1], al[1]);
            if (kt < 6) {
                p = *(const float2*)(r0 + c0 + 8); split_pack2_fast(p.x, p.y, ah[2], al[2]);
                p = *(const float2*)(r1 + c0 + 8); split_pack2_fast(p.x, p.y, ah[3], al[3]);
            } else {
                ah[2] = al[2] = ah[3] = al[3] = 0u;
            }
            #pragma unroll
            for (int j = 0; j < 4; j++) {
                uint4 Bw = B1u[(j * 7 + kt) * 32 + lane];
                uint4 Bb = B1u[((j + 4) * 7 + kt) * 32 + lane];
                mma16816(cw[j], ah, Bw.x, Bw.y);
                mma16816(cw[j], al, Bw.x, Bw.y);
                mma16816(cw[j], ah, Bw.z, Bw.w);
                mma16816(cb[j], ah, Bb.x, Bb.y);
                mma16816(cb[j], al, Bb.x, Bb.y);
                mma16816(cb[j], ah, Bb.z, Bb.w);
            }
        }

        // ---- epilogue 1: bias + pov mix + relu -> layer-0 A frags ----
        const int prow = pass * STAGE_ROWS + warp * 16 + q;
        float pv0 = spov[prow];
        float pv1 = spov[prow + 8];
        float pm0 = 1.f - pv0, pm1 = 1.f - pv1;

        uint32_t a0h[4][4], a0l[4][4];
        #pragma unroll
        for (int j = 0; j < 4; j++) {
            float4 bi = bia1[j * 32 + lane];
            float w0 = cw[j][0] + bi.x, w1 = cw[j][1] + bi.y;
            float w2_ = cw[j][2] + bi.x, w3 = cw[j][3] + bi.y;
            float bb0 = cb[j][0] + bi.z, bb1 = cb[j][1] + bi.w;
            float bb2 = cb[j][2] + bi.z, bb3 = cb[j][3] + bi.w;
            float vA0 = fmaxf(fmaf(pv0, w0, pm0 * bb0), 0.f);
            float vA1 = fmaxf(fmaf(pv0, w1, pm0 * bb1), 0.f);
            float vA2 = fmaxf(fmaf(pv1, w2_, pm1 * bb2), 0.f);
            float vA3 = fmaxf(fmaf(pv1, w3, pm1 * bb3), 0.f);
            float vB0 = fmaxf(fmaf(pv0, bb0, pm0 * w0), 0.f);
            float vB1 = fmaxf(fmaf(pv0, bb1, pm0 * w1), 0.f);
            float vB2 = fmaxf(fmaf(pv1, bb2, pm1 * w2_), 0.f);
            float vB3 = fmaxf(fmaf(pv1, bb3, pm1 * w3), 0.f);
            int ktw = j >> 1;
            int pos = (j & 1) ? 2 : 0;
            split_pack2_fast(vA0, vA1, a0h[ktw][pos],     a0l[ktw][pos]);
            split_pack2_fast(vA2, vA3, a0h[ktw][pos + 1], a0l[ktw][pos + 1]);
            split_pack2_fast(vB0, vB1, a0h[ktw + 2][pos],     a0l[ktw + 2][pos]);
            split_pack2_fast(vB2, vB3, a0h[ktw + 2][pos + 1], a0l[ktw + 2][pos + 1]);
        }

        // ---- layer 0 ----
        float xv[4][4];
        uint32_t a1h[2][4], a1l[2][4];
        #pragma unroll
        for (int n = 0; n < 4; n++) {
            float c0v[4] = {0.f, 0.f, 0.f, 0.f};
            #pragma unroll
            for (int kt = 0; kt < 4; kt++) {
                uint4 Bq = B0u[(n * 4 + kt) * 32 + lane];
                mma16816(c0v, a0h[kt], Bq.x, Bq.y);
                mma16816(c0v, a0l[kt], Bq.x, Bq.y);
                mma16816(c0v, a0h[kt], Bq.z, Bq.w);
            }
            float2 bz = b0f[n * 32 + lane];
            float x0 = fmaxf(c0v[0] + bz.x, 0.f);
            float x1 = fmaxf(c0v[1] + bz.y, 0.f);
            float x2 = fmaxf(c0v[2] + bz.x, 0.f);
            float x3 = fmaxf(c0v[3] + bz.y, 0.f);
            xv[n][0] = x0; xv[n][1] = x1; xv[n][2] = x2; xv[n][3] = x3;
            int ktw = n >> 1;
            int pos = (n & 1) ? 2 : 0;
            split_pack2_fast(x0, x1, a1h[ktw][pos],     a1l[ktw][pos]);
            split_pack2_fast(x2, x3, a1h[ktw][pos + 1], a1l[ktw][pos + 1]);
        }

        // ---- layer 1b + final dot ----
        float rA = 0.f, rB = 0.f;
        #pragma unroll
        for (int n = 0; n < 4; n++) {
            float c1[4] = {0.f, 0.f, 0.f, 0.f};
            #pragma unroll
            for (int kt = 0; kt < 2; kt++) {
                uint4 Bq = B1bu[(n * 2 + kt) * 32 + lane];
                mma16816(c1, a1h[kt], Bq.x, Bq.y);
                mma16816(c1, a1l[kt], Bq.x, Bq.y);
                mma16816(c1, a1h[kt], Bq.z, Bq.w);
            }
            float2 bz = b1f[n * 32 + lane];
            float y0 = fmaxf(c1[0] + bz.x, 0.f);
            float y1 = fmaxf(c1[1] + bz.y, 0.f);
            float y2 = fmaxf(c1[2] + bz.x, 0.f);
            float y3 = fmaxf(c1[3] + bz.y, 0.f);
            float4 w2 = w2f[n * 32 + lane];
            rA = fmaf(w2.x, xv[n][0], rA); rA = fmaf(w2.y, xv[n][1], rA);
            rA = fmaf(w2.z, y0, rA);       rA = fmaf(w2.w, y1, rA);
            rB = fmaf(w2.x, xv[n][2], rB); rB = fmaf(w2.y, xv[n][3], rB);
            rB = fmaf(w2.z, y2, rB);       rB = fmaf(w2.w, y3, rB);
        }
        rA += __shfl_xor_sync(0xFFFFFFFFu, rA, 1);
        rA += __shfl_xor_sync(0xFFFFFFFFu, rA, 2);
        rB += __shfl_xor_sync(0xFFFFFFFFu, rB, 1);
        rB += __shfl_xor_sync(0xFFFFFFFFu, rB, 2);
        if (qp == 0) {
            const float b2v = *((const float*)(packS + OFF_B2));
            long long rowA = pbase + warp * 16 + q;
            long long rowB = rowA + 8;
            if (rowA < (long long)Btot) out[rowA] = rA + b2v;
            if (rowB < (long long)Btot) out[rowB] = rB + b2v;
        }
    }
}

// ======================= launch =======================
extern "C" void kernel_launch(void* const* d_in, const int* in_sizes, int n_in,
                              void* d_out, int out_size) {
    const float* pov   = (const float*)d_in[0];
    const float* white = (const float*)d_in[1];
    const float* black = (const float*)d_in[2];
    const float* Ww = (const float*)d_in[3];
    const float* bw = (const float*)d_in[4];
    const float* Wb = (const float*)d_in[5];
    const float* bb = (const float*)d_in[6];
    const float* W0 = (const float*)d_in[7];
    const float* b0 = (const float*)d_in[8];
    const float* W1 = (const float*)d_in[9];
    const float* b1 = (const float*)d_in[10];
    const float* W2 = (const float*)d_in[11];
    const float* b2 = (const float*)d_in[12];
    const int B = in_sizes[0];

    prep_kernel<<<1, 256>>>(Ww, Wb, W0, W1, bw, bb, b0, b1, W2, b2);

    cudaFuncSetAttribute(nnue_main, cudaFuncAttributeMaxDynamicSharedMemorySize, SMEM_BYTES);
    int grid = (B + ROWS_CTA - 1) / ROWS_CTA;
    nnue_main<<<grid, NT, SMEM_BYTES>>>(pov, white, black, (float*)d_out, B);
}